// round 8
// baseline (speedup 1.0000x reference)
#include <cuda_runtime.h>
#include <math.h>

// maps: [128, 33, 224, 224] fp32  -> d_in[0]
// w1:   [100, 33]            fp32 -> d_in[1]
// w2:   [10, 100]            fp32 -> d_in[2]
// out:  x_sun [128,33] (4224 floats) then x_son stack [9,128,10] (11520 floats)

#define PLANE_ELEMS  (224 * 224)       // 50176
#define PLANE_VEC4   (PLANE_ELEMS / 4) // 12544
#define POOL_THREADS 256
#define POOL_ITERS   (PLANE_VEC4 / POOL_THREADS) // 49, exact
#define CHANNELS     33
#define BATCH        128
#define N_PLANES     (BATCH * CHANNELS) // 4224
#define X_SUN_ELEMS  (BATCH * CHANNELS) // 4224

__device__ int g_ctr[BATCH];   // zero at load; head (sole consumer) resets

// ---------------------------------------------------------------------------
// Kernel 1: global average pool per (b,c) plane. One block per plane.
// Epilogue: release-publish this plane into the per-batch arrival counter.
// ---------------------------------------------------------------------------
__global__ __launch_bounds__(POOL_THREADS, 8)
void pool_kernel(const float4* __restrict__ maps, float* __restrict__ out)
{
    const int plane = blockIdx.x;
    const float4* p = maps + (size_t)plane * PLANE_VEC4;
    const int tid = threadIdx.x;

    float s = 0.0f;
#pragma unroll
    for (int i = 0; i < POOL_ITERS; i++) {
        float4 v = __ldcs(&p[tid + i * POOL_THREADS]);   // streaming: no reuse
        s += (v.x + v.y) + (v.z + v.w);
    }

#pragma unroll
    for (int off = 16; off > 0; off >>= 1)
        s += __shfl_down_sync(0xFFFFFFFFu, s, off);

    __shared__ float warp_sums[POOL_THREADS / 32];
    const int lane = tid & 31;
    const int wid  = tid >> 5;
    if (lane == 0) warp_sums[wid] = s;
    __syncthreads();

    if (tid == 0) {
        float t = 0.0f;
#pragma unroll
        for (int w = 0; w < POOL_THREADS / 32; w++) t += warp_sums[w];
        out[plane] = t * (1.0f / (float)PLANE_ELEMS);
        __threadfence();                          // release the plane value
        atomicAdd(&g_ctr[plane / CHANNELS], 1);   // arrival tick
    }
}

// ---------------------------------------------------------------------------
// Kernel 2: MLP head, launched CONCURRENTLY on a forked stream.
// One block per batch (320 threads = 10 warps); the block spin-waits for its
// batch's 33 plane arrivals, so it runs during the pool's drain waves.
// Single consumer per counter -> reset is race-free.
// ---------------------------------------------------------------------------
__global__ __launch_bounds__(320, 6)
void head_kernel(const float* __restrict__ w1,
                 const float* __restrict__ w2,
                 float* __restrict__ out)
{
    const int b    = blockIdx.x;
    const int tid  = threadIdx.x;
    const int lane = tid & 31;
    const int wrp  = tid >> 5;      // 0..9 = output index o

    __shared__ float t33[CHANNELS];
    __shared__ float g[100];
    __shared__ float votes[10][104];

    // wait for all 33 planes of batch b
    if (tid == 0) {
        while (atomicAdd(&g_ctr[b], 0) < CHANNELS) { }
        __threadfence();            // acquire
    }
    __syncthreads();

    if (tid < CHANNELS)
        t33[tid] = tanhf(__ldcg(&out[b * CHANNELS + tid]));
    __syncthreads();

    if (tid == 0)
        g_ctr[b] = 0;               // reset for next graph replay

    // fc1 + relu
    if (tid < 100) {
        float s = 0.0f;
#pragma unroll
        for (int c = 0; c < CHANNELS; c++)
            s = fmaf(t33[c], w1[tid * CHANNELS + c], s);
        g[tid] = fmaxf(s, 0.0f);
    }
    __syncthreads();

    // ---- per-warp: votes for output o = wrp ----
    const int o = wrp;
    float v0 = g[lane]      * w2[o * 100 + lane];
    float v1 = g[lane + 32] * w2[o * 100 + lane + 32];
    float v2 = g[lane + 64] * w2[o * 100 + lane + 64];
    float v3 = (lane < 4) ? g[lane + 96] * w2[o * 100 + lane + 96] : 0.0f;

    votes[o][lane]      = v0;
    votes[o][lane + 32] = v1;
    votes[o][lane + 64] = v2;
    if (lane < 4) votes[o][lane + 96] = v3;
    __syncwarp();

    // rank via counting (strict total order with index tie-break)
    int r0 = 0, r1 = 0, r2 = 0, r3 = 0;
    const int i0 = lane, i1 = lane + 32, i2 = lane + 64, i3 = lane + 96;
#pragma unroll 4
    for (int j = 0; j < 100; j++) {
        float u = votes[o][j];                 // broadcast read
        r0 += (u > v0) | ((u == v0) & (j < i0));
        r1 += (u > v1) | ((u == v1) & (j < i1));
        r2 += (u > v2) | ((u == v2) & (j < i2));
        r3 += (u > v3) | ((u == v3) & (j < i3));
    }
    if (lane >= 4) r3 = 100;

    const int KS[8] = {3, 4, 5, 6, 7, 10, 15, 20};
    float sk[9];
#pragma unroll
    for (int k = 0; k < 8; k++) {
        float a = 0.0f;
        if (r0 < KS[k]) a += v0;
        if (r1 < KS[k]) a += v1;
        if (r2 < KS[k]) a += v2;
        if (r3 < KS[k]) a += v3;
        sk[k] = a;
    }
    sk[8] = v0 + v1 + v2 + v3;                 // dense pass

#pragma unroll
    for (int k = 0; k < 9; k++) {
#pragma unroll
        for (int off = 16; off > 0; off >>= 1)
            sk[k] += __shfl_down_sync(0xFFFFFFFFu, sk[k], off);
    }

    if (lane == 0) {
        float* son = out + X_SUN_ELEMS;
#pragma unroll
        for (int k = 0; k < 9; k++)
            son[k * (BATCH * 10) + b * 10 + o] = sk[k];
    }
}

// ---------------------------------------------------------------------------
extern "C" void kernel_launch(void* const* d_in, const int* in_sizes, int n_in,
                              void* d_out, int out_size)
{
    const float4* maps = (const float4*)d_in[0];
    const float*  w1   = (const float*)d_in[1];
    const float*  w2   = (const float*)d_in[2];
    float* out = (float*)d_out;

    // Try a forked-stream launch so pool and head become PARALLEL branches of
    // the captured graph; the data dependency is carried by g_ctr[] counters.
    cudaStream_t s = 0;
    cudaEvent_t ev_fork = 0, ev_join = 0;
    bool forked = true;
    if (cudaStreamCreateWithFlags(&s, cudaStreamNonBlocking) != cudaSuccess) forked = false;
    if (forked && cudaEventCreateWithFlags(&ev_fork, cudaEventDisableTiming) != cudaSuccess) forked = false;
    if (forked && cudaEventCreateWithFlags(&ev_join, cudaEventDisableTiming) != cudaSuccess) forked = false;

    if (forked && cudaEventRecord(ev_fork, 0) != cudaSuccess) forked = false;       // before pool
    pool_kernel<<<N_PLANES, POOL_THREADS>>>(maps, out);

    if (forked && cudaStreamWaitEvent(s, ev_fork, 0) != cudaSuccess) forked = false;
    if (forked) {
        head_kernel<<<BATCH, 320, 0, s>>>(w1, w2, out);
        if (cudaGetLastError() != cudaSuccess) forked = false;
    }
    if (forked && cudaEventRecord(ev_join, s) != cudaSuccess) forked = false;
    if (forked && cudaStreamWaitEvent(0, ev_join, 0) != cudaSuccess) forked = false;

    if (!forked) {
        // Sequential fallback: head after pool on the capture stream.
        // Counters are already complete, so the spin exits immediately.
        (void)cudaGetLastError();
        head_kernel<<<BATCH, 320>>>(w1, w2, out);
    }
    // streams/events are intentionally leaked (2 calls total; no device alloc)
}

// round 9
// speedup vs baseline: 1.0582x; 1.0582x over previous
#include <cuda_runtime.h>
#include <math.h>

// maps: [128, 33, 224, 224] fp32  -> d_in[0]
// w1:   [100, 33]            fp32 -> d_in[1]
// w2:   [10, 100]            fp32 -> d_in[2]
// out:  x_sun [128,33] (4224 floats) then x_son stack [9,128,10] (11520 floats)

#define PLANE_ELEMS  (224 * 224)       // 50176
#define PLANE_VEC4   (PLANE_ELEMS / 4) // 12544
#define NTHREADS     256
#define POOL_ITERS   (PLANE_VEC4 / NTHREADS) // 49, exact
#define CHANNELS     33
#define BATCH        128
#define N_PLANES     (BATCH * CHANNELS) // 4224
#define X_SUN_ELEMS  (BATCH * CHANNELS) // 4224

__device__ int g_ctr[BATCH];   // zero at load; head (sole consumer) resets

// shared memory union: pool uses 8 floats, head uses ~4.8 KB
struct HeadSmem {
    float t33[CHANNELS];
    float g[100];
    float votes[10][104];
};
union FusedSmem {
    float warp_sums[NTHREADS / 32];
    HeadSmem h;
};

// ---------------------------------------------------------------------------
// Head body, isolated via noinline so pool codegen stays clean.
// 256 threads: warps 0-7 -> outputs 0-7; warps 0,1 also -> outputs 8,9.
// ---------------------------------------------------------------------------
__device__ __noinline__ void head_body(int b,
                                       const float* __restrict__ w1,
                                       const float* __restrict__ w2,
                                       float* __restrict__ out,
                                       FusedSmem* sm)
{
    const int tid  = threadIdx.x;
    const int lane = tid & 31;
    const int wrp  = tid >> 5;

    // wait for all 33 planes of batch b
    if (tid == 0) {
        while (atomicAdd(&g_ctr[b], 0) < CHANNELS) { }
        __threadfence();            // acquire
    }
    __syncthreads();

    if (tid < CHANNELS)
        sm->h.t33[tid] = tanhf(__ldcg(&out[b * CHANNELS + tid]));
    __syncthreads();

    if (tid == 0)
        g_ctr[b] = 0;               // reset for next graph replay

    // fc1 + relu
    if (tid < 100) {
        float s = 0.0f;
#pragma unroll
        for (int c = 0; c < CHANNELS; c++)
            s = fmaf(sm->h.t33[c], w1[tid * CHANNELS + c], s);
        sm->h.g[tid] = fmaxf(s, 0.0f);
    }
    __syncthreads();

    const int KS[8] = {3, 4, 5, 6, 7, 10, 15, 20};
    float* son = out + X_SUN_ELEMS;

    const int n_o = (wrp < 2) ? 2 : 1;
    for (int t = 0; t < n_o; t++) {
        const int o = wrp + t * 8;

        float v0 = sm->h.g[lane]      * w2[o * 100 + lane];
        float v1 = sm->h.g[lane + 32] * w2[o * 100 + lane + 32];
        float v2 = sm->h.g[lane + 64] * w2[o * 100 + lane + 64];
        float v3 = (lane < 4) ? sm->h.g[lane + 96] * w2[o * 100 + lane + 96] : 0.0f;

        sm->h.votes[o][lane]      = v0;
        sm->h.votes[o][lane + 32] = v1;
        sm->h.votes[o][lane + 64] = v2;
        if (lane < 4) sm->h.votes[o][lane + 96] = v3;
        __syncwarp();

        // rank via counting (strict total order with index tie-break)
        int r0 = 0, r1 = 0, r2 = 0, r3 = 0;
        const int i0 = lane, i1 = lane + 32, i2 = lane + 64, i3 = lane + 96;
#pragma unroll 4
        for (int j = 0; j < 100; j++) {
            float u = sm->h.votes[o][j];       // broadcast read
            r0 += (u > v0) | ((u == v0) & (j < i0));
            r1 += (u > v1) | ((u == v1) & (j < i1));
            r2 += (u > v2) | ((u == v2) & (j < i2));
            r3 += (u > v3) | ((u == v3) & (j < i3));
        }
        if (lane >= 4) r3 = 100;

        float sk[9];
#pragma unroll
        for (int k = 0; k < 8; k++) {
            float a = 0.0f;
            if (r0 < KS[k]) a += v0;
            if (r1 < KS[k]) a += v1;
            if (r2 < KS[k]) a += v2;
            if (r3 < KS[k]) a += v3;
            sk[k] = a;
        }
        sk[8] = v0 + v1 + v2 + v3;             // dense pass

#pragma unroll
        for (int k = 0; k < 9; k++) {
#pragma unroll
            for (int off = 16; off > 0; off >>= 1)
                sk[k] += __shfl_down_sync(0xFFFFFFFFu, sk[k], off);
        }

        if (lane == 0) {
#pragma unroll
            for (int k = 0; k < 9; k++)
                son[k * (BATCH * 10) + b * 10 + o] = sk[k];
        }
        __syncwarp();
    }
}

// ---------------------------------------------------------------------------
// Fused grid: bids [0, 4224) = pool (one block per plane);
//             bids [4224, 4352) = head (one block per batch), scheduled only
// in the final wave (ascending-bid dispatch), overlapping the pool drain.
// ---------------------------------------------------------------------------
__global__ __launch_bounds__(NTHREADS, 8)
void fused_kernel(const float4* __restrict__ maps,
                  const float* __restrict__ w1,
                  const float* __restrict__ w2,
                  float* __restrict__ out)
{
    __shared__ FusedSmem sm;
    const int bid = blockIdx.x;
    const int tid = threadIdx.x;

    if (bid < N_PLANES) {
        // ---------------- pool path (pure; head isolated behind noinline) ---
        const float4* p = maps + (size_t)bid * PLANE_VEC4;

        float s = 0.0f;
#pragma unroll
        for (int i = 0; i < POOL_ITERS; i++) {
            float4 v = __ldcs(&p[tid + i * NTHREADS]);   // streaming
            s += (v.x + v.y) + (v.z + v.w);
        }

#pragma unroll
        for (int off = 16; off > 0; off >>= 1)
            s += __shfl_down_sync(0xFFFFFFFFu, s, off);

        const int lane = tid & 31;
        const int wid  = tid >> 5;
        if (lane == 0) sm.warp_sums[wid] = s;
        __syncthreads();

        if (tid == 0) {
            float t = 0.0f;
#pragma unroll
            for (int w = 0; w < NTHREADS / 32; w++) t += sm.warp_sums[w];
            out[bid] = t * (1.0f / (float)PLANE_ELEMS);
            __threadfence();                          // release the value
            atomicAdd(&g_ctr[bid / CHANNELS], 1);     // arrival tick
        }
        return;
    }

    // ---------------- head path ----------------
    head_body(bid - N_PLANES, w1, w2, out, &sm);
}

// ---------------------------------------------------------------------------
extern "C" void kernel_launch(void* const* d_in, const int* in_sizes, int n_in,
                              void* d_out, int out_size)
{
    const float4* maps = (const float4*)d_in[0];
    const float*  w1   = (const float*)d_in[1];
    const float*  w2   = (const float*)d_in[2];
    float* out = (float*)d_out;

    fused_kernel<<<N_PLANES + BATCH, NTHREADS>>>(maps, w1, w2, out);
}

// round 10
// speedup vs baseline: 1.1278x; 1.0658x over previous
#include <cuda_runtime.h>
#include <math.h>

// maps: [128, 33, 224, 224] fp32  -> d_in[0]
// w1:   [100, 33]            fp32 -> d_in[1]
// w2:   [10, 100]            fp32 -> d_in[2]
// out:  x_sun [128,33] (4224 floats) then x_son stack [9,128,10] (11520 floats)

#define PLANE_ELEMS  (224 * 224)       // 50176
#define PLANE_VEC4   (PLANE_ELEMS / 4) // 12544
#define POOL_THREADS 256
#define POOL_ITERS   (PLANE_VEC4 / POOL_THREADS) // 49, exact
#define CHANNELS     33
#define BATCH        128
#define N_PLANES     (BATCH * CHANNELS) // 4224
#define X_SUN_ELEMS  (BATCH * CHANNELS) // 4224
#define DELAY_THRESH 3968              // release head dispatch at ~94% done

__device__ int g_ctr[BATCH];   // per-batch arrivals; head block b resets
__device__ int g_total;        // total plane arrivals; head block 0 resets

// ---------------------------------------------------------------------------
// Kernel 1: global average pool per (b,c) plane. One block per plane.
// Proven 7.4 TB/s configuration; epilogue releases per-batch + total counters.
// ---------------------------------------------------------------------------
__global__ __launch_bounds__(POOL_THREADS, 8)
void pool_kernel(const float4* __restrict__ maps, float* __restrict__ out)
{
    const int plane = blockIdx.x;
    const float4* p = maps + (size_t)plane * PLANE_VEC4;
    const int tid = threadIdx.x;

    float s = 0.0f;
#pragma unroll
    for (int i = 0; i < POOL_ITERS; i++) {
        float4 v = __ldcs(&p[tid + i * POOL_THREADS]);   // streaming: no reuse
        s += (v.x + v.y) + (v.z + v.w);
    }

#pragma unroll
    for (int off = 16; off > 0; off >>= 1)
        s += __shfl_down_sync(0xFFFFFFFFu, s, off);

    __shared__ float warp_sums[POOL_THREADS / 32];
    const int lane = tid & 31;
    const int wid  = tid >> 5;
    if (lane == 0) warp_sums[wid] = s;
    __syncthreads();

    if (tid == 0) {
        float t = 0.0f;
#pragma unroll
        for (int w = 0; w < POOL_THREADS / 32; w++) t += warp_sums[w];
        out[plane] = t * (1.0f / (float)PLANE_ELEMS);
        __threadfence();                          // release the plane value
        atomicAdd(&g_ctr[plane / CHANNELS], 1);   // per-batch arrival
        atomicAdd(&g_total, 1);                   // global arrival
    }
}

// ---------------------------------------------------------------------------
// Delay kernel (forked stream): 1 block, 32 threads. Holds the head's
// dispatch until the pool is ~94% complete, so head blocks only occupy SM
// slots during the pool's drain wave.
// ---------------------------------------------------------------------------
__global__ void delay_kernel()
{
    if (threadIdx.x == 0) {
        while (atomicAdd(&g_total, 0) < DELAY_THRESH)
            __nanosleep(256);
    }
}

// ---------------------------------------------------------------------------
// Kernel 2: MLP head. One block per batch (320 threads = 10 warps).
// Spin-waits on its batch's 33 arrivals; warp w computes output o=w via
// rank-by-counting. Block 0 additionally retires g_total for graph replay.
// ---------------------------------------------------------------------------
__global__ __launch_bounds__(320, 6)
void head_kernel(const float* __restrict__ w1,
                 const float* __restrict__ w2,
                 float* __restrict__ out)
{
    const int b    = blockIdx.x;
    const int tid  = threadIdx.x;
    const int lane = tid & 31;
    const int wrp  = tid >> 5;      // 0..9 = output index o

    __shared__ float t33[CHANNELS];
    __shared__ float g[100];
    __shared__ float votes[10][104];

    // wait for all 33 planes of batch b
    if (tid == 0) {
        while (atomicAdd(&g_ctr[b], 0) < CHANNELS)
            __nanosleep(128);
        __threadfence();            // acquire
    }
    __syncthreads();

    if (tid < CHANNELS)
        t33[tid] = tanhf(__ldcg(&out[b * CHANNELS + tid]));
    __syncthreads();

    if (tid == 0)
        atomicExch(&g_ctr[b], 0);   // reset for next graph replay

    // fc1 + relu
    if (tid < 100) {
        float s = 0.0f;
#pragma unroll
        for (int c = 0; c < CHANNELS; c++)
            s = fmaf(t33[c], w1[tid * CHANNELS + c], s);
        g[tid] = fmaxf(s, 0.0f);
    }
    __syncthreads();

    // ---- per-warp: votes for output o = wrp ----
    const int o = wrp;
    float v0 = g[lane]      * w2[o * 100 + lane];
    float v1 = g[lane + 32] * w2[o * 100 + lane + 32];
    float v2 = g[lane + 64] * w2[o * 100 + lane + 64];
    float v3 = (lane < 4) ? g[lane + 96] * w2[o * 100 + lane + 96] : 0.0f;

    votes[o][lane]      = v0;
    votes[o][lane + 32] = v1;
    votes[o][lane + 64] = v2;
    if (lane < 4) votes[o][lane + 96] = v3;
    __syncwarp();

    // rank via counting (strict total order with index tie-break)
    int r0 = 0, r1 = 0, r2 = 0, r3 = 0;
    const int i0 = lane, i1 = lane + 32, i2 = lane + 64, i3 = lane + 96;
#pragma unroll 4
    for (int j = 0; j < 100; j++) {
        float u = votes[o][j];                 // broadcast read
        r0 += (u > v0) | ((u == v0) & (j < i0));
        r1 += (u > v1) | ((u == v1) & (j < i1));
        r2 += (u > v2) | ((u == v2) & (j < i2));
        r3 += (u > v3) | ((u == v3) & (j < i3));
    }
    if (lane >= 4) r3 = 100;

    const int KS[8] = {3, 4, 5, 6, 7, 10, 15, 20};
    float sk[9];
#pragma unroll
    for (int k = 0; k < 8; k++) {
        float a = 0.0f;
        if (r0 < KS[k]) a += v0;
        if (r1 < KS[k]) a += v1;
        if (r2 < KS[k]) a += v2;
        if (r3 < KS[k]) a += v3;
        sk[k] = a;
    }
    sk[8] = v0 + v1 + v2 + v3;                 // dense pass

#pragma unroll
    for (int k = 0; k < 9; k++) {
#pragma unroll
        for (int off = 16; off > 0; off >>= 1)
            sk[k] += __shfl_down_sync(0xFFFFFFFFu, sk[k], off);
    }

    if (lane == 0) {
        float* son = out + X_SUN_ELEMS;
#pragma unroll
        for (int k = 0; k < 9; k++)
            son[k * (BATCH * 10) + b * 10 + o] = sk[k];
    }

    // block 0: retire the total counter once the pool has fully finished
    // (all increments done when == N_PLANES, so the reset is race-free)
    if (b == 0 && tid == 0) {
        while (atomicAdd(&g_total, 0) < N_PLANES)
            __nanosleep(128);
        atomicExch(&g_total, 0);
    }
}

// ---------------------------------------------------------------------------
extern "C" void kernel_launch(void* const* d_in, const int* in_sizes, int n_in,
                              void* d_out, int out_size)
{
    const float4* maps = (const float4*)d_in[0];
    const float*  w1   = (const float*)d_in[1];
    const float*  w2   = (const float*)d_in[2];
    float* out = (float*)d_out;

    // Fork: [delay -> head] runs as a parallel graph branch; delay gates the
    // head's dispatch into the pool's drain window.
    cudaStream_t s = 0;
    cudaEvent_t ev_fork = 0, ev_join = 0;
    bool forked = true;
    if (cudaStreamCreateWithFlags(&s, cudaStreamNonBlocking) != cudaSuccess) forked = false;
    if (forked && cudaEventCreateWithFlags(&ev_fork, cudaEventDisableTiming) != cudaSuccess) forked = false;
    if (forked && cudaEventCreateWithFlags(&ev_join, cudaEventDisableTiming) != cudaSuccess) forked = false;

    if (forked && cudaEventRecord(ev_fork, 0) != cudaSuccess) forked = false;   // before pool
    pool_kernel<<<N_PLANES, POOL_THREADS>>>(maps, out);

    if (forked && cudaStreamWaitEvent(s, ev_fork, 0) != cudaSuccess) forked = false;
    if (forked) {
        delay_kernel<<<1, 32, 0, s>>>();
        head_kernel<<<BATCH, 320, 0, s>>>(w1, w2, out);
        if (cudaGetLastError() != cudaSuccess) forked = false;
    }
    if (forked && cudaEventRecord(ev_join, s) != cudaSuccess) forked = false;
    if (forked && cudaStreamWaitEvent(0, ev_join, 0) != cudaSuccess) forked = false;

    if (!forked) {
        // Sequential fallback: counters complete -> spins exit immediately.
        (void)cudaGetLastError();
        head_kernel<<<BATCH, 320>>>(w1, w2, out);
    }
    // streams/events intentionally persist (created once per capture; no device alloc)
}

// round 11
// speedup vs baseline: 1.2101x; 1.0730x over previous
#include <cuda_runtime.h>
#include <math.h>

// maps: [128, 33, 224, 224] fp32  -> d_in[0]
// w1:   [100, 33]            fp32 -> d_in[1]
// w2:   [10, 100]            fp32 -> d_in[2]
// out:  x_sun [128,33] (4224 floats) then x_son stack [9,128,10] (11520 floats)

#define PLANE_ELEMS  (224 * 224)       // 50176
#define PLANE_VEC4   (PLANE_ELEMS / 4) // 12544
#define CHUNKS_PER_PLANE 7
#define CHUNK_VEC4   (PLANE_VEC4 / CHUNKS_PER_PLANE) // 1792, exact
#define POOL_THREADS 256
#define CHUNK_ITERS  (CHUNK_VEC4 / POOL_THREADS)     // 7, exact
#define CHANNELS     33
#define BATCH        128
#define N_PLANES     (BATCH * CHANNELS)              // 4224
#define N_CHUNKS     (N_PLANES * CHUNKS_PER_PLANE)   // 29568
#define X_SUN_ELEMS  (BATCH * CHANNELS)              // 4224

__device__ float g_partial[N_CHUNKS];   // per-chunk partial sums (deterministic)

// ---------------------------------------------------------------------------
// Kernel 1: partial-sum reduction, one block per 1/7-plane chunk.
// 29568 blocks / 1184 slots = 24.97 waves -> wave-quantization waste ~0.1%
// (vs 10.8% at one-block-per-plane). No atomics/counters in the epilogue.
// ---------------------------------------------------------------------------
__global__ __launch_bounds__(POOL_THREADS, 8)
void pool_kernel(const float4* __restrict__ maps)
{
    const int chunk = blockIdx.x;
    const float4* p = maps + (size_t)chunk * CHUNK_VEC4;
    const int tid = threadIdx.x;

    float s = 0.0f;
#pragma unroll
    for (int i = 0; i < CHUNK_ITERS; i++) {
        float4 v = __ldcs(&p[tid + i * POOL_THREADS]);   // streaming: no reuse
        s += (v.x + v.y) + (v.z + v.w);
    }

#pragma unroll
    for (int off = 16; off > 0; off >>= 1)
        s += __shfl_down_sync(0xFFFFFFFFu, s, off);

    __shared__ float warp_sums[POOL_THREADS / 32];
    const int lane = tid & 31;
    const int wid  = tid >> 5;
    if (lane == 0) warp_sums[wid] = s;
    __syncthreads();

    if (tid == 0) {
        float t = 0.0f;
#pragma unroll
        for (int w = 0; w < POOL_THREADS / 32; w++) t += warp_sums[w];
        g_partial[chunk] = t;
    }
}

// ---------------------------------------------------------------------------
// Kernel 2: MLP head. One block per batch (320 threads = 10 warps).
// Combines the 7 chunk partials per channel, writes x_sun, then warp w
// computes output o=w via rank-by-counting on u64 sortable keys.
// ---------------------------------------------------------------------------
__global__ __launch_bounds__(320, 6)
void head_kernel(const float* __restrict__ w1,
                 const float* __restrict__ w2,
                 float* __restrict__ out)
{
    const int b    = blockIdx.x;
    const int tid  = threadIdx.x;
    const int lane = tid & 31;
    const int wrp  = tid >> 5;      // 0..9 = output index o

    __shared__ float t33[CHANNELS];
    __shared__ float g[100];
    __shared__ unsigned long long keys[10][104];

    // combine partials -> mean -> x_sun + tanh
    if (tid < CHANNELS) {
        const float* pp = &g_partial[(b * CHANNELS + tid) * CHUNKS_PER_PLANE];
        float m = 0.0f;
#pragma unroll
        for (int c = 0; c < CHUNKS_PER_PLANE; c++) m += pp[c];
        m *= (1.0f / (float)PLANE_ELEMS);
        out[b * CHANNELS + tid] = m;    // x_sun
        t33[tid] = tanhf(m);
    }
    __syncthreads();

    // fc1 + relu
    if (tid < 100) {
        float s = 0.0f;
#pragma unroll
        for (int c = 0; c < CHANNELS; c++)
            s = fmaf(t33[c], w1[tid * CHANNELS + c], s);
        g[tid] = fmaxf(s, 0.0f);
    }
    __syncthreads();

    // ---- per-warp: votes for output o = wrp ----
    const int o = wrp;
    float v0 = g[lane]      * w2[o * 100 + lane];
    float v1 = g[lane + 32] * w2[o * 100 + lane + 32];
    float v2 = g[lane + 64] * w2[o * 100 + lane + 64];
    float v3 = (lane < 4) ? g[lane + 96] * w2[o * 100 + lane + 96] : 0.0f;

    // monotonic sortable u64 keys (strict total order via index low bits)
    auto mkkey = [](float v, int idx) {
        unsigned int u = __float_as_uint(v);
        u = (u & 0x80000000u) ? ~u : (u | 0x80000000u);
        return ((unsigned long long)u << 32) | (unsigned)idx;
    };
    unsigned long long k0 = mkkey(v0, lane);
    unsigned long long k1 = mkkey(v1, lane + 32);
    unsigned long long k2 = mkkey(v2, lane + 64);
    unsigned long long k3 = mkkey(v3, lane + 96);

    keys[o][lane]      = k0;
    keys[o][lane + 32] = k1;
    keys[o][lane + 64] = k2;
    if (lane < 4) keys[o][lane + 96] = k3;
    __syncwarp();

    // rank = # keys strictly greater (distinct keys -> permutation ranks)
    int r0 = 0, r1 = 0, r2 = 0, r3 = 0;
#pragma unroll 4
    for (int j = 0; j < 100; j++) {
        unsigned long long u = keys[o][j];     // broadcast read
        r0 += (u > k0);
        r1 += (u > k1);
        r2 += (u > k2);
        r3 += (u > k3);
    }
    if (lane >= 4) r3 = 100;                   // non-existent value

    const int KS[8] = {3, 4, 5, 6, 7, 10, 15, 20};
    float sk[9];
#pragma unroll
    for (int k = 0; k < 8; k++) {
        float a = 0.0f;
        if (r0 < KS[k]) a += v0;
        if (r1 < KS[k]) a += v1;
        if (r2 < KS[k]) a += v2;
        if (r3 < KS[k]) a += v3;
        sk[k] = a;
    }
    sk[8] = v0 + v1 + v2 + v3;                 // dense pass

#pragma unroll
    for (int k = 0; k < 9; k++) {
#pragma unroll
        for (int off = 16; off > 0; off >>= 1)
            sk[k] += __shfl_down_sync(0xFFFFFFFFu, sk[k], off);
    }

    if (lane == 0) {
        float* son = out + X_SUN_ELEMS;
#pragma unroll
        for (int k = 0; k < 9; k++)
            son[k * (BATCH * 10) + b * 10 + o] = sk[k];
    }
}

// ---------------------------------------------------------------------------
extern "C" void kernel_launch(void* const* d_in, const int* in_sizes, int n_in,
                              void* d_out, int out_size)
{
    const float4* maps = (const float4*)d_in[0];
    const float*  w1   = (const float*)d_in[1];
    const float*  w2   = (const float*)d_in[2];
    float* out = (float*)d_out;

    pool_kernel<<<N_CHUNKS, POOL_THREADS>>>(maps);
    head_kernel<<<BATCH, 320>>>(w1, w2, out);
}

// round 12
// speedup vs baseline: 1.2105x; 1.0003x over previous
#include <cuda_runtime.h>
#include <math.h>

// maps: [128, 33, 224, 224] fp32  -> d_in[0]
// w1:   [100, 33]            fp32 -> d_in[1]
// w2:   [10, 100]            fp32 -> d_in[2]
// out:  x_sun [128,33] (4224 floats) then x_son stack [9,128,10] (11520 floats)

#define PLANE_ELEMS  (224 * 224)       // 50176
#define PLANE_VEC4   (PLANE_ELEMS / 4) // 12544
#define CHUNKS_PER_PLANE 7
#define CHUNK_VEC4   (PLANE_VEC4 / CHUNKS_PER_PLANE) // 1792, exact
#define POOL_THREADS 256
#define CHUNK_ITERS  (CHUNK_VEC4 / POOL_THREADS)     // 7, exact
#define CHANNELS     33
#define BATCH        128
#define N_PLANES     (BATCH * CHANNELS)              // 4224
#define N_CHUNKS     (N_PLANES * CHUNKS_PER_PLANE)   // 29568
#define X_SUN_ELEMS  (BATCH * CHANNELS)              // 4224
#define PARTIALS_PER_BATCH (CHANNELS * CHUNKS_PER_PLANE) // 231

__device__ float g_partial[N_CHUNKS];   // per-chunk partial sums (deterministic)

// ---------------------------------------------------------------------------
// Kernel 1: partial-sum reduction, one block per 1/7-plane chunk.
// 29568 blocks / ~1184 slots -> ~25 waves, wave-quantization waste ~0.1%.
// Measured ~7.6 TB/s (~95% of HBM spec).
// ---------------------------------------------------------------------------
__global__ __launch_bounds__(POOL_THREADS, 8)
void pool_kernel(const float4* __restrict__ maps)
{
    const int chunk = blockIdx.x;
    const float4* p = maps + (size_t)chunk * CHUNK_VEC4;
    const int tid = threadIdx.x;

    float s = 0.0f;
#pragma unroll
    for (int i = 0; i < CHUNK_ITERS; i++) {
        float4 v = __ldcs(&p[tid + i * POOL_THREADS]);   // streaming: no reuse
        s += (v.x + v.y) + (v.z + v.w);
    }

#pragma unroll
    for (int off = 16; off > 0; off >>= 1)
        s += __shfl_down_sync(0xFFFFFFFFu, s, off);

    __shared__ float warp_sums[POOL_THREADS / 32];
    const int lane = tid & 31;
    const int wid  = tid >> 5;
    if (lane == 0) warp_sums[wid] = s;
    __syncthreads();

    if (tid == 0) {
        float t = 0.0f;
#pragma unroll
        for (int w = 0; w < POOL_THREADS / 32; w++) t += warp_sums[w];
        g_partial[chunk] = t;
    }
}

// ---------------------------------------------------------------------------
// Kernel 2: MLP head. One block per batch (320 threads = 10 warps).
// Phase 0 stages ALL global data (w1, w2, partials) into smem in a single
// parallel load wave (one DRAM round-trip); all compute then runs from smem.
// ---------------------------------------------------------------------------
__global__ __launch_bounds__(320, 6)
void head_kernel(const float* __restrict__ w1,
                 const float* __restrict__ w2,
                 float* __restrict__ out)
{
    const int b    = blockIdx.x;
    const int tid  = threadIdx.x;
    const int lane = tid & 31;
    const int wrp  = tid >> 5;      // 0..9 = output index o

    __shared__ float w1s[100 * CHANNELS];   // 3300 floats
    __shared__ float w2s[10 * 100];         // 1000 floats
    __shared__ float ps[PARTIALS_PER_BATCH];// 231 floats
    __shared__ float t33[CHANNELS];
    __shared__ float g[100];
    __shared__ unsigned long long keys[10][104];

    // ---- phase 0: single parallel load wave (maximize MLP) ----
#pragma unroll
    for (int i = tid; i < 100 * CHANNELS; i += 320)
        w1s[i] = w1[i];
#pragma unroll
    for (int i = tid; i < 10 * 100; i += 320)
        w2s[i] = w2[i];
    if (tid < PARTIALS_PER_BATCH)
        ps[tid] = g_partial[b * PARTIALS_PER_BATCH + tid];
    __syncthreads();

    // ---- combine partials -> mean -> x_sun + tanh ----
    if (tid < CHANNELS) {
        float m = 0.0f;
#pragma unroll
        for (int c = 0; c < CHUNKS_PER_PLANE; c++)
            m += ps[tid * CHUNKS_PER_PLANE + c];
        m *= (1.0f / (float)PLANE_ELEMS);
        out[b * CHANNELS + tid] = m;    // x_sun
        t33[tid] = tanhf(m);
    }
    __syncthreads();

    // ---- fc1 + relu (stride-33 smem: 33 % 32 == 1 -> conflict-free) ----
    if (tid < 100) {
        float s = 0.0f;
#pragma unroll
        for (int c = 0; c < CHANNELS; c++)
            s = fmaf(t33[c], w1s[tid * CHANNELS + c], s);
        g[tid] = fmaxf(s, 0.0f);
    }
    __syncthreads();

    // ---- per-warp: votes for output o = wrp ----
    const int o = wrp;
    float v0 = g[lane]      * w2s[o * 100 + lane];
    float v1 = g[lane + 32] * w2s[o * 100 + lane + 32];
    float v2 = g[lane + 64] * w2s[o * 100 + lane + 64];
    float v3 = (lane < 4) ? g[lane + 96] * w2s[o * 100 + lane + 96] : 0.0f;

    // monotonic sortable u64 keys (strict total order via index low bits)
    auto mkkey = [](float v, int idx) {
        unsigned int u = __float_as_uint(v);
        u = (u & 0x80000000u) ? ~u : (u | 0x80000000u);
        return ((unsigned long long)u << 32) | (unsigned)idx;
    };
    unsigned long long k0 = mkkey(v0, lane);
    unsigned long long k1 = mkkey(v1, lane + 32);
    unsigned long long k2 = mkkey(v2, lane + 64);
    unsigned long long k3 = mkkey(v3, lane + 96);

    keys[o][lane]      = k0;
    keys[o][lane + 32] = k1;
    keys[o][lane + 64] = k2;
    if (lane < 4) keys[o][lane + 96] = k3;
    __syncwarp();

    // rank = # keys strictly greater (distinct keys -> permutation ranks)
    int r0 = 0, r1 = 0, r2 = 0, r3 = 0;
#pragma unroll 4
    for (int j = 0; j < 100; j++) {
        unsigned long long u = keys[o][j];     // broadcast read
        r0 += (u > k0);
        r1 += (u > k1);
        r2 += (u > k2);
        r3 += (u > k3);
    }
    if (lane >= 4) r3 = 100;                   // non-existent value

    const int KS[8] = {3, 4, 5, 6, 7, 10, 15, 20};
    float sk[9];
#pragma unroll
    for (int k = 0; k < 8; k++) {
        float a = 0.0f;
        if (r0 < KS[k]) a += v0;
        if (r1 < KS[k]) a += v1;
        if (r2 < KS[k]) a += v2;
        if (r3 < KS[k]) a += v3;
        sk[k] = a;
    }
    sk[8] = v0 + v1 + v2 + v3;                 // dense pass

#pragma unroll
    for (int k = 0; k < 9; k++) {
#pragma unroll
        for (int off = 16; off > 0; off >>= 1)
            sk[k] += __shfl_down_sync(0xFFFFFFFFu, sk[k], off);
    }

    if (lane == 0) {
        float* son = out + X_SUN_ELEMS;
#pragma unroll
        for (int k = 0; k < 9; k++)
            son[k * (BATCH * 10) + b * 10 + o] = sk[k];
    }
}

// ---------------------------------------------------------------------------
extern "C" void kernel_launch(void* const* d_in, const int* in_sizes, int n_in,
                              void* d_out, int out_size)
{
    const float4* maps = (const float4*)d_in[0];
    const float*  w1   = (const float*)d_in[1];
    const float*  w2   = (const float*)d_in[2];
    float* out = (float*)d_out;

    pool_kernel<<<N_CHUNKS, POOL_THREADS>>>(maps);
    head_kernel<<<BATCH, 320>>>(w1, w2, out);
}

// round 13
// speedup vs baseline: 1.2127x; 1.0018x over previous
#include <cuda_runtime.h>
#include <math.h>

// maps: [128, 33, 224, 224] fp32  -> d_in[0]
// w1:   [100, 33]            fp32 -> d_in[1]
// w2:   [10, 100]            fp32 -> d_in[2]
// out:  x_sun [128,33] (4224 floats) then x_son stack [9,128,10] (11520 floats)

#define PLANE_ELEMS  (224 * 224)       // 50176
#define PLANE_VEC4   (PLANE_ELEMS / 4) // 12544
#define CHUNKS_PER_PLANE 7
#define CHUNK_VEC4   (PLANE_VEC4 / CHUNKS_PER_PLANE) // 1792, exact
#define POOL_THREADS 256
#define CHUNK_ITERS  (CHUNK_VEC4 / POOL_THREADS)     // 7, exact
#define CHANNELS     33
#define BATCH        128
#define N_PLANES     (BATCH * CHANNELS)              // 4224
#define N_CHUNKS     (N_PLANES * CHUNKS_PER_PLANE)   // 29568
#define X_SUN_ELEMS  (BATCH * CHANNELS)              // 4224
#define PARTIALS_PER_BATCH (CHANNELS * CHUNKS_PER_PLANE) // 231
#define HEAD_THREADS 640

__device__ float g_partial[N_CHUNKS];   // per-chunk partial sums (deterministic)

// ---------------------------------------------------------------------------
// Kernel 1: partial-sum reduction, one block per 1/7-plane chunk.
// ~25 waves -> wave-quantization waste ~0.1%. Measured ~7.6 TB/s (95% spec).
// ---------------------------------------------------------------------------
__global__ __launch_bounds__(POOL_THREADS, 8)
void pool_kernel(const float4* __restrict__ maps)
{
    const int chunk = blockIdx.x;
    const float4* p = maps + (size_t)chunk * CHUNK_VEC4;
    const int tid = threadIdx.x;

    float s = 0.0f;
#pragma unroll
    for (int i = 0; i < CHUNK_ITERS; i++) {
        float4 v = __ldcs(&p[tid + i * POOL_THREADS]);   // streaming: no reuse
        s += (v.x + v.y) + (v.z + v.w);
    }

#pragma unroll
    for (int off = 16; off > 0; off >>= 1)
        s += __shfl_down_sync(0xFFFFFFFFu, s, off);

    __shared__ float warp_sums[POOL_THREADS / 32];
    const int lane = tid & 31;
    const int wid  = tid >> 5;
    if (lane == 0) warp_sums[wid] = s;
    __syncthreads();

    if (tid == 0) {
        float t = 0.0f;
#pragma unroll
        for (int w = 0; w < POOL_THREADS / 32; w++) t += warp_sums[w];
        g_partial[chunk] = t;
    }
}

// ---------------------------------------------------------------------------
// Kernel 2: MLP head. One block per batch, 640 threads = 20 warps = a warp
// PAIR per output. Each warp of pair (o,h) partial-ranks the same 4 owned
// values against its 50-key half; ranks combine via one int4 smem exchange.
// All global data staged to smem in a single load wave.
// ---------------------------------------------------------------------------
__global__ __launch_bounds__(HEAD_THREADS, 3)
void head_kernel(const float* __restrict__ w1,
                 const float* __restrict__ w2,
                 float* __restrict__ out)
{
#if __CUDA_ARCH__ >= 900
    cudaGridDependencySynchronize();   // PDL: dispatch prefetched vs pool end
#endif
    const int b    = blockIdx.x;
    const int tid  = threadIdx.x;
    const int lane = tid & 31;
    const int wrp  = tid >> 5;      // 0..19
    const int o    = wrp >> 1;      // output 0..9
    const int h    = wrp & 1;       // half 0/1

    __shared__ float w1s[100 * CHANNELS];    // 3300 floats
    __shared__ float w2s[10 * 100];          // 1000 floats
    __shared__ float ps[PARTIALS_PER_BATCH]; // 231 floats
    __shared__ float t33[CHANNELS];
    __shared__ float g[100];
    __shared__ unsigned long long keys[10][104];
    __shared__ int4 rp[10][32];              // h=1 partial ranks

    // ---- phase 0: single parallel load wave ----
    for (int i = tid; i < 100 * CHANNELS; i += HEAD_THREADS)
        w1s[i] = w1[i];
    for (int i = tid; i < 10 * 100; i += HEAD_THREADS)
        w2s[i] = w2[i];
    if (tid < PARTIALS_PER_BATCH)
        ps[tid] = g_partial[b * PARTIALS_PER_BATCH + tid];
    __syncthreads();

    // ---- combine partials -> mean -> x_sun + tanh ----
    if (tid < CHANNELS) {
        float m = 0.0f;
#pragma unroll
        for (int c = 0; c < CHUNKS_PER_PLANE; c++)
            m += ps[tid * CHUNKS_PER_PLANE + c];
        m *= (1.0f / (float)PLANE_ELEMS);
        out[b * CHANNELS + tid] = m;    // x_sun
        t33[tid] = tanhf(m);
    }
    __syncthreads();

    // ---- fc1 + relu (stride 33 -> conflict-free smem) ----
    if (tid < 100) {
        float s = 0.0f;
#pragma unroll
        for (int c = 0; c < CHANNELS; c++)
            s = fmaf(t33[c], w1s[tid * CHANNELS + c], s);
        g[tid] = fmaxf(s, 0.0f);
    }
    __syncthreads();

    // ---- votes (both warps of the pair compute the same owned values) ----
    float v0 = g[lane]      * w2s[o * 100 + lane];
    float v1 = g[lane + 32] * w2s[o * 100 + lane + 32];
    float v2 = g[lane + 64] * w2s[o * 100 + lane + 64];
    float v3 = (lane < 4) ? g[lane + 96] * w2s[o * 100 + lane + 96] : 0.0f;

    auto mkkey = [](float v, int idx) {
        unsigned int u = __float_as_uint(v);
        u = (u & 0x80000000u) ? ~u : (u | 0x80000000u);
        return ((unsigned long long)u << 32) | (unsigned)idx;
    };
    unsigned long long k0 = mkkey(v0, lane);
    unsigned long long k1 = mkkey(v1, lane + 32);
    unsigned long long k2 = mkkey(v2, lane + 64);
    unsigned long long k3 = mkkey(v3, lane + 96);

    if (h == 0) {
        keys[o][lane]      = k0;
        keys[o][lane + 32] = k1;
        keys[o][lane + 64] = k2;
        if (lane < 4) keys[o][lane + 96] = k3;
    }
    __syncthreads();

    // ---- partial ranks over this warp's 50-key half ----
    int r0 = 0, r1 = 0, r2 = 0, r3 = 0;
    {
        const int base = h * 50;
#pragma unroll 5
        for (int j = 0; j < 50; j++) {
            unsigned long long u = keys[o][base + j];   // broadcast read
            r0 += (u > k0);
            r1 += (u > k1);
            r2 += (u > k2);
            r3 += (u > k3);
        }
    }
    if (h == 1)
        rp[o][lane] = make_int4(r0, r1, r2, r3);
    __syncthreads();

    if (h == 0) {
        int4 q = rp[o][lane];
        r0 += q.x; r1 += q.y; r2 += q.z; r3 += q.w;
        if (lane >= 4) r3 = 100;                        // non-existent value

        const int KS[8] = {3, 4, 5, 6, 7, 10, 15, 20};
        float sk[9];
#pragma unroll
        for (int k = 0; k < 8; k++) {
            float a = 0.0f;
            if (r0 < KS[k]) a += v0;
            if (r1 < KS[k]) a += v1;
            if (r2 < KS[k]) a += v2;
            if (r3 < KS[k]) a += v3;
            sk[k] = a;
        }
        sk[8] = v0 + v1 + v2 + v3;                      // dense pass

#pragma unroll
        for (int k = 0; k < 9; k++) {
#pragma unroll
            for (int off = 16; off > 0; off >>= 1)
                sk[k] += __shfl_down_sync(0xFFFFFFFFu, sk[k], off);
        }

        if (lane == 0) {
            float* son = out + X_SUN_ELEMS;
#pragma unroll
            for (int k = 0; k < 9; k++)
                son[k * (BATCH * 10) + b * 10 + o] = sk[k];
        }
    }
}

// ---------------------------------------------------------------------------
extern "C" void kernel_launch(void* const* d_in, const int* in_sizes, int n_in,
                              void* d_out, int out_size)
{
    const float4* maps = (const float4*)d_in[0];
    const float*  w1   = (const float*)d_in[1];
    const float*  w2   = (const float*)d_in[2];
    float* out = (float*)d_out;

    pool_kernel<<<N_CHUNKS, POOL_THREADS>>>(maps);

    // head with programmatic dependent launch (hide the launch gap)
    cudaLaunchConfig_t cfg = {};
    cfg.gridDim  = dim3(BATCH, 1, 1);
    cfg.blockDim = dim3(HEAD_THREADS, 1, 1);
    cfg.dynamicSmemBytes = 0;
    cfg.stream = 0;
    cudaLaunchAttribute attr[1];
    attr[0].id = cudaLaunchAttributeProgrammaticStreamSerialization;
    attr[0].val.programmaticStreamSerializationAllowed = 1;
    cfg.attrs = attr;
    cfg.numAttrs = 1;

    cudaError_t e = cudaLaunchKernelEx(&cfg, head_kernel, w1, w2, out);
    if (e != cudaSuccess) {
        (void)cudaGetLastError();                   // clear, fall back
        head_kernel<<<BATCH, HEAD_THREADS>>>(w1, w2, out);
    }
}